// round 4
// baseline (speedup 1.0000x reference)
#include <cuda_runtime.h>
#include <cstdint>
#include <cstddef>

#define BB 8
#define CC 256
#define HH 64
#define WW 64
#define GG 8
#define CGR 32
#define KKT 9
#define OO 256
#define NPIX (BB*HH*WW)        // 32768
#define KC (CC*KKT)            // 2304
#define CO1 216
#define HWSZ (HH*WW)           // 4096

// -------- scratch (static device globals; ~75MB total) --------------------
__device__ __align__(16) float  g_Y[(size_t)CO1 * NPIX];          // conv1 out [216][32768]
__device__ __align__(16) float4 g_wq[(size_t)(GG*KKT) * NPIX];    // bilinear wts * attn
__device__ __align__(16) int    g_idx[(size_t)(GG*KKT) * NPIX];   // packed clamped indices

// -------- fused implicit GEMM (TN): C[m, co] = sum_k A[k][m] * W[co][k] ---
// EPI==0: A = on-the-fly im2col of x; W = (w_off|w_attn); out = g_Y [co][n]
// EPI==1: A = on-the-fly modulated bilinear samples; W = w_out; out = NCHW
template <int EPI>
__global__ __launch_bounds__(256) void gemm_fused(
    const float* __restrict__ x,
    const float* __restrict__ Wa,
    const float* __restrict__ Wb,
    const float* __restrict__ ba,
    const float* __restrict__ bb,
    float* __restrict__ Cout, int CO)
{
    // Output pointer resolved IN DEVICE CODE (device-global address space).
    float* __restrict__ outp = (EPI == 0) ? g_Y : Cout;

    __shared__ float As[8][128];
    __shared__ float Bs[8][132];   // padded transposed weight tile

    const int tid = threadIdx.x;
    const int m0 = blockIdx.x * 128;
    const int n0 = blockIdx.y * 128;
    const int b  = m0 >> 12;          // batch constant per block (4096 pix/image)
    const int tm = tid >> 4;          // 0..15
    const int tn = tid & 15;          // 0..15

    float acc[8][8];
#pragma unroll
    for (int i = 0; i < 8; i++)
#pragma unroll
        for (int j = 0; j < 8; j++) acc[i][j] = 0.f;

    // A producer mapping: k-row r = tid>>5 (0..7), cols c0 + 32*j
    const int r  = tid >> 5;
    const int c0 = tid & 31;
    // W loader mapping
    const int wco = n0 + (tid >> 1);
    const int wk  = (tid & 1) * 4;
    const int wcs = tid >> 1;

    const float* wrow = nullptr;
    if (EPI == 0) {
        if (wco < 144)      wrow = Wa + (size_t)wco * KC;
        else if (wco < CO)  wrow = Wb + (size_t)(wco - 144) * KC;
    } else {
        if (wco < CO)       wrow = Wa + (size_t)wco * KC;
    }

    for (int k0 = 0; k0 < KC; k0 += 8) {
        const int k = k0 + r;
        float av[4];

        if (EPI == 0) {
            // implicit im2col: k -> (ci, tap)
            int ci = k / 9;
            int kk = k - ci * 9;
            int k3 = kk / 3;
            int dy = k3 - 1;
            int dx = kk - k3 * 3 - 1;
            const float* xb = x + ((size_t)(b * CC + ci)) * HWSZ;
#pragma unroll
            for (int j = 0; j < 4; j++) {
                int m  = m0 + c0 + 32 * j;
                int hw = m & 4095;
                int h  = hw >> 6, w = hw & 63;
                int y  = h + dy, xx = w + dx;
                av[j] = ((unsigned)y < (unsigned)HH && (unsigned)xx < (unsigned)WW)
                            ? xb[y * WW + xx] : 0.f;
            }
        } else {
            // implicit modulated deformable sample: k -> (g, cg, tap)
            int g   = k / 288;
            int rem = k - g * 288;
            int cg  = rem / 9;
            int kk  = rem - cg * 9;
            size_t sbase = (size_t)(g * KKT + kk) * NPIX;
            const float* xb = x + ((size_t)(b * CC + g * CGR + cg)) * HWSZ;
#pragma unroll
            for (int j = 0; j < 4; j++) {
                int m = m0 + c0 + 32 * j;
                size_t s = sbase + m;
                float4 wq = g_wq[s];
                int pk = g_idx[s];
                int r0  = pk & 63;
                int r1  = (pk >> 6) & 63;
                int cc0 = (pk >> 12) & 63;
                int cc1 = (pk >> 18) & 63;
                av[j] = wq.x * xb[(r0 << 6) + cc0]
                      + wq.y * xb[(r0 << 6) + cc1]
                      + wq.z * xb[(r1 << 6) + cc0]
                      + wq.w * xb[(r1 << 6) + cc1];
            }
        }

        float4 w4 = wrow ? *(const float4*)(wrow + k0 + wk)
                         : make_float4(0.f, 0.f, 0.f, 0.f);

        __syncthreads();
#pragma unroll
        for (int j = 0; j < 4; j++) As[r][c0 + 32 * j] = av[j];
        Bs[wk + 0][wcs] = w4.x;
        Bs[wk + 1][wcs] = w4.y;
        Bs[wk + 2][wcs] = w4.z;
        Bs[wk + 3][wcs] = w4.w;
        __syncthreads();

#pragma unroll
        for (int kk = 0; kk < 8; kk++) {
            float4 a0 = *(const float4*)&As[kk][tm * 8];
            float4 a1 = *(const float4*)&As[kk][tm * 8 + 4];
            float4 b0 = *(const float4*)&Bs[kk][tn * 8];
            float4 b1 = *(const float4*)&Bs[kk][tn * 8 + 4];
            float af[8] = {a0.x, a0.y, a0.z, a0.w, a1.x, a1.y, a1.z, a1.w};
            float bf[8] = {b0.x, b0.y, b0.z, b0.w, b1.x, b1.y, b1.z, b1.w};
#pragma unroll
            for (int i = 0; i < 8; i++)
#pragma unroll
                for (int j = 0; j < 8; j++)
                    acc[i][j] += af[i] * bf[j];
        }
    }

    // epilogue
#pragma unroll
    for (int j = 0; j < 8; j++) {
        int co = n0 + tn * 8 + j;
        if (co >= CO) continue;
        if (EPI == 0) {
            float bias = (co < 144) ? ba[co] : bb[co - 144];
#pragma unroll
            for (int i = 0; i < 8; i++) {
                int m = m0 + tm * 8 + i;
                outp[(size_t)co * NPIX + m] = acc[i][j] + bias;
            }
        } else {
            float bias = ba[co];
#pragma unroll
            for (int i = 0; i < 8; i++) {
                int m  = m0 + tm * 8 + i;
                int hw = m & 4095;
                outp[((size_t)(b * OO + co)) * HWSZ + hw] = acc[i][j] + bias;
            }
        }
    }
}

// -------- K2: softmax + offsets -> packed bilinear weights/indices --------
__global__ __launch_bounds__(256) void offmask_kernel() {
    int n = blockIdx.x * 256 + threadIdx.x;
    int g = blockIdx.y;   // 0..7
    int hw = n & 4095;
    int h = hw >> 6, w = hw & 63;

    float lg[KKT];
    float mx = -1e30f;
#pragma unroll
    for (int kk = 0; kk < KKT; kk++) {
        lg[kk] = g_Y[(size_t)(144 + g * KKT + kk) * NPIX + n];
        mx = fmaxf(mx, lg[kk]);
    }
    float s = 0.f;
#pragma unroll
    for (int kk = 0; kk < KKT; kk++) { lg[kk] = __expf(lg[kk] - mx); s += lg[kk]; }
    float inv = 1.f / s;

#pragma unroll
    for (int kk = 0; kk < KKT; kk++) {
        float a  = lg[kk] * inv;
        float dy = g_Y[(size_t)(g * 18 + 2 * kk    ) * NPIX + n];
        float dx = g_Y[(size_t)(g * 18 + 2 * kk + 1) * NPIX + n];
        float py = (float)(h - 1 + kk / 3) + dy;
        float px = (float)(w - 1 + kk % 3) + dx;

        float y0f = floorf(py), x0f = floorf(px);
        float fy = py - y0f, fx = px - x0f;
        // clamp BEFORE int conversion (safe: far-out taps have zero weight)
        y0f = fminf(fmaxf(y0f, -2.f), 65.f);
        x0f = fminf(fmaxf(x0f, -2.f), 65.f);
        int y0 = (int)y0f, x0 = (int)x0f;

        bool vy0 = (unsigned)y0       < (unsigned)HH;
        bool vy1 = (unsigned)(y0 + 1) < (unsigned)HH;
        bool vx0 = (unsigned)x0       < (unsigned)WW;
        bool vx1 = (unsigned)(x0 + 1) < (unsigned)WW;

        float w00 = (vy0 && vx0) ? (1.f - fy) * (1.f - fx) * a : 0.f;
        float w01 = (vy0 && vx1) ? (1.f - fy) * fx * a : 0.f;
        float w10 = (vy1 && vx0) ? fy * (1.f - fx) * a : 0.f;
        float w11 = (vy1 && vx1) ? fy * fx * a : 0.f;

        int r0  = min(max(y0,     0), HH - 1);
        int r1  = min(max(y0 + 1, 0), HH - 1);
        int cc0 = min(max(x0,     0), WW - 1);
        int cc1 = min(max(x0 + 1, 0), WW - 1);
        int pack = r0 | (r1 << 6) | (cc0 << 12) | (cc1 << 18);

        size_t o = (size_t)(g * KKT + kk) * NPIX + n;
        g_wq[o]  = make_float4(w00, w01, w10, w11);
        g_idx[o] = pack;
    }
}

// --------------------------------------------------------------------------
extern "C" void kernel_launch(void* const* d_in, const int* in_sizes, int n_in,
                              void* d_out, int out_size) {
    // Bind inputs BY ELEMENT COUNT (robust to harness input ordering).
    const float* x      = nullptr;
    const float* w_off  = nullptr;
    const float* b_off  = nullptr;
    const float* w_attn = nullptr;
    const float* b_attn = nullptr;
    const float* w_out  = nullptr;
    const float* b_out  = nullptr;
    for (int i = 0; i < n_in; i++) {
        const float* p = (const float*)d_in[i];
        switch (in_sizes[i]) {
            case 8388608: x      = p; break;
            case 331776:  w_off  = p; break;
            case 144:     b_off  = p; break;
            case 165888:  w_attn = p; break;
            case 72:      b_attn = p; break;
            case 589824:  w_out  = p; break;
            case 256:     b_out  = p; break;
            default: break;
        }
    }
    if (!x || !w_off || !b_off || !w_attn || !b_attn || !w_out || !b_out)
        return;
    float* out = (float*)d_out;

    // 1) offset/mask conv as fused implicit GEMM -> g_Y [216][32768]
    //    (output pointer resolved inside device code; nullptr placeholder)
    gemm_fused<0><<<dim3(NPIX / 128, 2), 256>>>(
        x, w_off, w_attn, b_off, b_attn, nullptr, CO1);

    // 2) softmax over taps + packed bilinear weights/indices
    offmask_kernel<<<dim3(NPIX / 256, GG), 256>>>();

    // 3) deformable conv as fused implicit GEMM -> NCHW out
    gemm_fused<1><<<dim3(NPIX / 128, 2), 256>>>(
        x, w_out, nullptr, b_out, nullptr, out, OO);
}

// round 6
// speedup vs baseline: 1.5025x; 1.5025x over previous
#include <cuda_runtime.h>
#include <cuda_bf16.h>
#include <cstdint>
#include <cstddef>

#define BB 8
#define CC 256
#define HH 64
#define WW 64
#define GG 8
#define CGR 32
#define KKT 9
#define OO 256
#define NPIX (BB*HH*WW)        // 32768
#define KC (CC*KKT)            // 2304
#define KW (KC/2)              // 1152 b32 words per row
#define CO1 216
#define HWSZ (HH*WW)           // 4096
#define NCH (KC/16)            // 144 k16 steps

// smem stage layout (bytes): Ah[128x32] Al[128x32] Bh[256x32] Bl[256x32]
#define AH_O 0
#define AL_O 4096
#define BH_O 8192
#define BL_O 16384
#define STG_B 24576
#define SMEM_TOT (2*STG_B)     // 49152

// -------- scratch (static device globals) ---------------------------------
__device__ __align__(16) float    g_Y[(size_t)CO1 * NPIX];          // conv1 out [216][32768]
__device__ __align__(16) float4   g_wq[(size_t)(GG*KKT) * NPIX];    // bilinear wts * attn
__device__ __align__(16) int      g_idx[(size_t)(GG*KKT) * NPIX];   // packed indices
__device__ __align__(16) uint32_t g_Bw[2][2][256 * KW];             // [gemm][hi/lo][n][kw]

// -------- helpers ---------------------------------------------------------
__device__ __forceinline__ uint32_t smem_u32(const void* p) {
    uint32_t a;
    asm("{ .reg .u64 t; cvta.to.shared.u64 t, %1; cvt.u32.u64 %0, t; }"
        : "=r"(a) : "l"(p));
    return a;
}
__device__ __forceinline__ void ldsm4(uint32_t* r, uint32_t addr) {
    asm volatile("ldmatrix.sync.aligned.m8n8.x4.shared.b16 {%0,%1,%2,%3}, [%4];"
        : "=r"(r[0]), "=r"(r[1]), "=r"(r[2]), "=r"(r[3]) : "r"(addr));
}
__device__ __forceinline__ void mma16816(float* c, const uint32_t* a,
                                         uint32_t b0, uint32_t b1) {
    asm volatile(
        "mma.sync.aligned.m16n8k16.row.col.f32.bf16.bf16.f32 "
        "{%0,%1,%2,%3}, {%4,%5,%6,%7}, {%8,%9}, {%0,%1,%2,%3};"
        : "+f"(c[0]), "+f"(c[1]), "+f"(c[2]), "+f"(c[3])
        : "r"(a[0]), "r"(a[1]), "r"(a[2]), "r"(a[3]), "r"(b0), "r"(b1));
}
__device__ __forceinline__ void split_bf16(float v, uint16_t& h, uint16_t& l) {
    __nv_bfloat16 hb = __float2bfloat16(v);
    float r = v - __bfloat162float(hb);
    __nv_bfloat16 lb = __float2bfloat16(r);
    h = *reinterpret_cast<uint16_t*>(&hb);
    l = *reinterpret_cast<uint16_t*>(&lb);
}

// -------- setup: split weights to bf16 hi/lo word pairs -------------------
__global__ __launch_bounds__(256) void stageB_kernel(
    const float* __restrict__ w_off, const float* __restrict__ w_attn,
    const float* __restrict__ w_out)
{
    int idx = blockIdx.x * 256 + threadIdx.x;     // over 2*256*1152
    int gemm = idx / (256 * KW);
    int rem  = idx - gemm * (256 * KW);
    int row  = rem / KW;
    int wd   = rem - row * KW;
    int k    = wd * 2;
    float v0 = 0.f, v1 = 0.f;
    if (gemm == 0) {
        if (row < 144) {
            v0 = w_off[(size_t)row * KC + k];
            v1 = w_off[(size_t)row * KC + k + 1];
        } else if (row < CO1) {
            v0 = w_attn[(size_t)(row - 144) * KC + k];
            v1 = w_attn[(size_t)(row - 144) * KC + k + 1];
        }
    } else {
        v0 = w_out[(size_t)row * KC + k];
        v1 = w_out[(size_t)row * KC + k + 1];
    }
    uint16_t h0, l0, h1, l1;
    split_bf16(v0, h0, l0);
    split_bf16(v1, h1, l1);
    g_Bw[gemm][0][row * KW + wd] = (uint32_t)h0 | ((uint32_t)h1 << 16);
    g_Bw[gemm][1][row * KW + wd] = (uint32_t)l0 | ((uint32_t)l1 << 16);
}

// -------- main warp-MMA implicit GEMM -------------------------------------
// EPI==0: A = im2col(x), B = staged (w_off|w_attn) -> g_Y [216][NPIX]
// EPI==1: A = modulated bilinear samples, B = staged w_out -> NCHW out
// CTA: 128 pixels x 256 channels, K = 2304. 512 threads / 16 warps (4m x 4n).
template <int EPI>
__global__ __launch_bounds__(512, 1) void mma_kernel(
    const float* __restrict__ x,
    const float* __restrict__ ba,
    const float* __restrict__ bb,
    float* __restrict__ Cout)
{
    extern __shared__ __align__(16) char smem[];
    const uint32_t sb = smem_u32(smem);
    const int tid  = threadIdx.x;
    const int lane = tid & 31;
    const int wid  = tid >> 5;
    const int wm   = wid & 3;      // warp m-index (x32)
    const int wn   = wid >> 2;     // warp n-index (x64)
    const int m0   = blockIdx.x * 128;
    const int b    = m0 >> 12;

    // producer mapping: this thread produces (m, word w) for m and m+64
    const int pm = tid >> 3;       // 0..63
    const int pw = tid & 7;        // word 0..7 (k = c*16 + pw*2)

    // ldmatrix per-lane invariant offsets
    const int rA   = lane & 15;
    const int segA = lane >> 4;
    const int rB   = (lane & 7) + ((lane & 16) ? 8 : 0);
    const int segB = (lane >> 3) & 1;
    int offAh[2], offBh[4];
#pragma unroll
    for (int mt = 0; mt < 2; mt++) {
        int row = wm * 32 + mt * 16 + rA;
        offAh[mt] = AH_O + row * 32 + (((segA * 4) ^ (rA & 4)) << 2);
    }
#pragma unroll
    for (int ntp = 0; ntp < 4; ntp++) {
        int row = wn * 64 + ntp * 16 + rB;
        offBh[ntp] = BH_O + row * 32 + (((segB * 4) ^ (rB & 4)) << 2);
    }

    // B-copy mapping: thread -> (n, 16B segment q)
    const int bn = tid >> 1;
    const int bq = tid & 1;

    float cr[2][8][4];
#pragma unroll
    for (int mt = 0; mt < 2; mt++)
#pragma unroll
        for (int nt = 0; nt < 8; nt++)
#pragma unroll
            for (int j = 0; j < 4; j++) cr[mt][nt][j] = 0.f;

    const uint32_t* __restrict__ Bh = g_Bw[EPI][0];
    const uint32_t* __restrict__ Bl = g_Bw[EPI][1];

    auto produce = [&](int c) {
        char* stp = smem + (c & 1) * STG_B;
        // ---- B tile copy (hi/lo), 16B per thread each ----
        {
            int gw = bn * KW + c * 8 + bq * 4;
            uint4 vh = *(const uint4*)&Bh[gw];
            uint4 vl = *(const uint4*)&Bl[gw];
            int dw = bn * 8 + ((bq * 4) ^ (bn & 4));
            *(uint4*)(stp + BH_O + dw * 4) = vh;
            *(uint4*)(stp + BL_O + dw * 4) = vl;
        }
        // ---- A tile produce: 2 (m, word) pairs ----
#pragma unroll
        for (int half = 0; half < 2; half++) {
            const int m  = pm + half * 64;
            const int mg = m0 + m;
            const int k  = c * 16 + pw * 2;
            float v0, v1;
            if (EPI == 0) {
                const int hh = (mg & 4095) >> 6;
                const int ww = mg & 63;
#pragma unroll
                for (int u = 0; u < 2; u++) {
                    int kk  = k + u;
                    int ci  = kk / 9;
                    int tap = kk - ci * 9;
                    int dy = tap / 3 - 1, dx = tap - (tap / 3) * 3 - 1;
                    int y = hh + dy, xx2 = ww + dx;
                    float v = ((unsigned)y < (unsigned)HH &&
                               (unsigned)xx2 < (unsigned)WW)
                        ? x[((size_t)(b * CC + ci) << 12) + (y << 6) + xx2] : 0.f;
                    if (u == 0) v0 = v; else v1 = v;
                }
            } else {
#pragma unroll
                for (int u = 0; u < 2; u++) {
                    int kk  = k + u;
                    int g   = kk / 288;
                    int rem = kk - g * 288;
                    int cg  = rem / 9;
                    int tap = rem - cg * 9;
                    const float* xb = x + ((size_t)(b * CC + g * CGR + cg) << 12);
                    size_t sidx = (size_t)(g * KKT + tap) * NPIX + mg;
                    float4 wq = g_wq[sidx];
                    int pk = g_idx[sidx];
                    int r0 = pk & 63, r1 = (pk >> 6) & 63;
                    int c0 = (pk >> 12) & 63, c1 = (pk >> 18) & 63;
                    float v = wq.x * xb[(r0 << 6) + c0] + wq.y * xb[(r0 << 6) + c1]
                            + wq.z * xb[(r1 << 6) + c0] + wq.w * xb[(r1 << 6) + c1];
                    if (u == 0) v0 = v; else v1 = v;
                }
            }
            uint16_t h0, l0, h1, l1;
            split_bf16(v0, h0, l0);
            split_bf16(v1, h1, l1);
            int dw = m * 8 + (pw ^ (m & 4));
            *(uint32_t*)(stp + AH_O + dw * 4) = (uint32_t)h0 | ((uint32_t)h1 << 16);
            *(uint32_t*)(stp + AL_O + dw * 4) = (uint32_t)l0 | ((uint32_t)l1 << 16);
        }
    };

    produce(0);
    __syncthreads();

    for (int c = 0; c < NCH; c++) {
        if (c + 1 < NCH) produce(c + 1);          // fills buf (c+1)&1

        // ---- consume buf c&1 ----
        const uint32_t stb = sb + (c & 1) * STG_B;
        uint32_t ah[2][4], al[2][4];
#pragma unroll
        for (int mt = 0; mt < 2; mt++) {
            ldsm4(ah[mt], stb + offAh[mt]);
            ldsm4(al[mt], stb + offAh[mt] + (AL_O - AH_O));
        }
#pragma unroll
        for (int ntp = 0; ntp < 4; ntp++) {
            uint32_t bh[4], bl[4];
            ldsm4(bh, stb + offBh[ntp]);
            ldsm4(bl, stb + offBh[ntp] + (BL_O - BH_O));
#pragma unroll
            for (int j = 0; j < 2; j++) {
                const int nt = ntp * 2 + j;
#pragma unroll
                for (int mt = 0; mt < 2; mt++) {
                    float* cc = cr[mt][nt];
                    mma16816(cc, ah[mt], bh[2 * j], bh[2 * j + 1]);
                    mma16816(cc, ah[mt], bl[2 * j], bl[2 * j + 1]);
                    mma16816(cc, al[mt], bh[2 * j], bh[2 * j + 1]);
                }
            }
        }
        __syncthreads();
    }

    // ---- epilogue ----
    const int eg = lane >> 2;       // 0..7
    const int et = lane & 3;        // 0..3
#pragma unroll
    for (int mt = 0; mt < 2; mt++) {
#pragma unroll
        for (int nt = 0; nt < 8; nt++) {
            const float* cc = cr[mt][nt];
            int mloc = wm * 32 + mt * 16 + eg;
            int co   = wn * 64 + nt * 8 + et * 2;
#pragma unroll
            for (int rr = 0; rr < 2; rr++) {       // row, row+8
                int m  = m0 + mloc + rr * 8;
#pragma unroll
                for (int cw = 0; cw < 2; cw++) {   // co, co+1
                    int c2 = co + cw;
                    float v = cc[rr * 2 + cw];
                    if (EPI == 0) {
                        if (c2 < CO1) {
                            float bias = (c2 < 144) ? ba[c2] : bb[c2 - 144];
                            g_Y[(size_t)c2 * NPIX + m] = v + bias;
                        }
                    } else {
                        Cout[((size_t)(b * OO + c2) << 12) + (m & 4095)] = v + ba[c2];
                    }
                }
            }
        }
    }
}

// -------- softmax + offsets -> packed bilinear weights/indices ------------
__global__ __launch_bounds__(256) void offmask_kernel() {
    int n = blockIdx.x * 256 + threadIdx.x;
    int g = blockIdx.y;
    int hw = n & 4095;
    int h = hw >> 6, w = hw & 63;

    float lg[KKT];
    float mx = -1e30f;
#pragma unroll
    for (int kk = 0; kk < KKT; kk++) {
        lg[kk] = g_Y[(size_t)(144 + g * KKT + kk) * NPIX + n];
        mx = fmaxf(mx, lg[kk]);
    }
    float s = 0.f;
#pragma unroll
    for (int kk = 0; kk < KKT; kk++) { lg[kk] = __expf(lg[kk] - mx); s += lg[kk]; }
    float inv = 1.f / s;

#pragma unroll
    for (int kk = 0; kk < KKT; kk++) {
        float a  = lg[kk] * inv;
        float dy = g_Y[(size_t)(g * 18 + 2 * kk    ) * NPIX + n];
        float dx = g_Y[(size_t)(g * 18 + 2 * kk + 1) * NPIX + n];
        float py = (float)(h - 1 + kk / 3) + dy;
        float px = (float)(w - 1 + kk % 3) + dx;

        float y0f = floorf(py), x0f = floorf(px);
        float fy = py - y0f, fx = px - x0f;
        y0f = fminf(fmaxf(y0f, -2.f), 65.f);
        x0f = fminf(fmaxf(x0f, -2.f), 65.f);
        int y0 = (int)y0f, x0 = (int)x0f;

        bool vy0 = (unsigned)y0       < (unsigned)HH;
        bool vy1 = (unsigned)(y0 + 1) < (unsigned)HH;
        bool vx0 = (unsigned)x0       < (unsigned)WW;
        bool vx1 = (unsigned)(x0 + 1) < (unsigned)WW;

        float w00 = (vy0 && vx0) ? (1.f - fy) * (1.f - fx) * a : 0.f;
        float w01 = (vy0 && vx1) ? (1.f - fy) * fx * a : 0.f;
        float w10 = (vy1 && vx0) ? fy * (1.f - fx) * a : 0.f;
        float w11 = (vy1 && vx1) ? fy * fx * a : 0.f;

        int r0  = min(max(y0,     0), HH - 1);
        int r1  = min(max(y0 + 1, 0), HH - 1);
        int cc0 = min(max(x0,     0), WW - 1);
        int cc1 = min(max(x0 + 1, 0), WW - 1);
        int pack = r0 | (r1 << 6) | (cc0 << 12) | (cc1 << 18);

        size_t o = (size_t)(g * KKT + kk) * NPIX + n;
        g_wq[o]  = make_float4(w00, w01, w10, w11);
        g_idx[o] = pack;
    }
}

// --------------------------------------------------------------------------
extern "C" void kernel_launch(void* const* d_in, const int* in_sizes, int n_in,
                              void* d_out, int out_size) {
    const float* x      = nullptr;
    const float* w_off  = nullptr;
    const float* b_off  = nullptr;
    const float* w_attn = nullptr;
    const float* b_attn = nullptr;
    const float* w_out  = nullptr;
    const float* b_out  = nullptr;
    for (int i = 0; i < n_in; i++) {
        const float* p = (const float*)d_in[i];
        switch (in_sizes[i]) {
            case 8388608: x      = p; break;
            case 331776:  w_off  = p; break;
            case 144:     b_off  = p; break;
            case 165888:  w_attn = p; break;
            case 72:      b_attn = p; break;
            case 589824:  w_out  = p; break;
            case 256:     b_out  = p; break;
            default: break;
        }
    }
    if (!x || !w_off || !b_off || !w_attn || !b_attn || !w_out || !b_out)
        return;
    float* out = (float*)d_out;

    cudaFuncSetAttribute(mma_kernel<0>,
        cudaFuncAttributeMaxDynamicSharedMemorySize, SMEM_TOT);
    cudaFuncSetAttribute(mma_kernel<1>,
        cudaFuncAttributeMaxDynamicSharedMemorySize, SMEM_TOT);

    // 0) stage weights: fp32 -> bf16 hi/lo packed word pairs
    stageB_kernel<<<(2 * 256 * KW) / 256, 256>>>(w_off, w_attn, w_out);

    // 1) offset/mask conv (HMMA) -> g_Y
    mma_kernel<0><<<NPIX / 128, 512, SMEM_TOT>>>(x, b_off, b_attn, nullptr);

    // 2) softmax + packed bilinear weights/indices
    offmask_kernel<<<dim3(NPIX / 256, GG), 256>>>();

    // 3) deformable conv (HMMA) -> NCHW out
    mma_kernel<1><<<NPIX / 128, 512, SMEM_TOT>>>(x, b_out, nullptr, out);
}

// round 7
// speedup vs baseline: 2.1232x; 1.4131x over previous
#include <cuda_runtime.h>
#include <cuda_bf16.h>
#include <cstdint>
#include <cstddef>

#define BB 8
#define CC 256
#define HH 64
#define WW 64
#define GG 8
#define CGR 32
#define KKT 9
#define OO 256
#define NPIX (BB*HH*WW)        // 32768
#define KC (CC*KKT)            // 2304
#define KW (KC/2)              // 1152 b32 words per row
#define CO1 216
#define HWSZ (HH*WW)           // 4096
#define NCH (KC/16)            // 144 k16 steps

// smem stage layout (bytes): A_h[4K] A_l[4K] B_h[8K] B_l[8K]
#define AH_O 0
#define AL_O 4096
#define BH_O 8192
#define BL_O 16384
#define STG_B 24576
#define SMEM_TOT (2*STG_B)     // 49152

// -------- scratch (static device globals, ~382MB) -------------------------
__device__ __align__(16) float    g_Y[(size_t)CO1 * NPIX];          // conv1 out
__device__ __align__(16) float4   g_wq[(size_t)(GG*KKT) * NPIX];    // bilinear wts * attn
__device__ __align__(16) int      g_idx[(size_t)(GG*KKT) * NPIX];   // packed indices
__device__ __align__(16) uint32_t g_Bw[2][2][256 * KW];             // [gemm][hi/lo][n][kw]
__device__ __align__(16) uint16_t g_Ah[(size_t)KC * NPIX];          // sampled A hi plane
__device__ __align__(16) uint16_t g_Al[(size_t)KC * NPIX];          // sampled A lo plane

// -------- helpers ---------------------------------------------------------
__device__ __forceinline__ uint32_t smem_u32(const void* p) {
    uint32_t a;
    asm("{ .reg .u64 t; cvta.to.shared.u64 t, %1; cvt.u32.u64 %0, t; }"
        : "=r"(a) : "l"(p));
    return a;
}
__device__ __forceinline__ void ldsm4(uint32_t* r, uint32_t addr) {
    asm volatile("ldmatrix.sync.aligned.m8n8.x4.shared.b16 {%0,%1,%2,%3}, [%4];"
        : "=r"(r[0]), "=r"(r[1]), "=r"(r[2]), "=r"(r[3]) : "r"(addr));
}
__device__ __forceinline__ void ldsm4t(uint32_t* r, uint32_t addr) {
    asm volatile("ldmatrix.sync.aligned.m8n8.x4.trans.shared.b16 {%0,%1,%2,%3}, [%4];"
        : "=r"(r[0]), "=r"(r[1]), "=r"(r[2]), "=r"(r[3]) : "r"(addr));
}
__device__ __forceinline__ void mma16816(float* c, const uint32_t* a,
                                         uint32_t b0, uint32_t b1) {
    asm volatile(
        "mma.sync.aligned.m16n8k16.row.col.f32.bf16.bf16.f32 "
        "{%0,%1,%2,%3}, {%4,%5,%6,%7}, {%8,%9}, {%0,%1,%2,%3};"
        : "+f"(c[0]), "+f"(c[1]), "+f"(c[2]), "+f"(c[3])
        : "r"(a[0]), "r"(a[1]), "r"(a[2]), "r"(a[3]), "r"(b0), "r"(b1));
}
__device__ __forceinline__ void split_bf16(float v, uint16_t& h, uint16_t& l) {
    __nv_bfloat16 hb = __float2bfloat16(v);
    float r = v - __bfloat162float(hb);
    __nv_bfloat16 lb = __float2bfloat16(r);
    h = *reinterpret_cast<uint16_t*>(&hb);
    l = *reinterpret_cast<uint16_t*>(&lb);
}

// -------- setup: split weights to bf16 hi/lo word pairs -------------------
__global__ __launch_bounds__(256) void stageB_kernel(
    const float* __restrict__ w_off, const float* __restrict__ w_attn,
    const float* __restrict__ w_out)
{
    int idx = blockIdx.x * 256 + threadIdx.x;     // over 2*256*1152
    int gemm = idx / (256 * KW);
    int rem  = idx - gemm * (256 * KW);
    int row  = rem / KW;
    int wd   = rem - row * KW;
    int k    = wd * 2;
    float v0 = 0.f, v1 = 0.f;
    if (gemm == 0) {
        if (row < 144) {
            v0 = w_off[(size_t)row * KC + k];
            v1 = w_off[(size_t)row * KC + k + 1];
        } else if (row < CO1) {
            v0 = w_attn[(size_t)(row - 144) * KC + k];
            v1 = w_attn[(size_t)(row - 144) * KC + k + 1];
        }
    } else {
        v0 = w_out[(size_t)row * KC + k];
        v1 = w_out[(size_t)row * KC + k + 1];
    }
    uint16_t h0, l0, h1, l1;
    split_bf16(v0, h0, l0);
    split_bf16(v1, h1, l1);
    g_Bw[gemm][0][row * KW + wd] = (uint32_t)h0 | ((uint32_t)h1 << 16);
    g_Bw[gemm][1][row * KW + wd] = (uint32_t)l0 | ((uint32_t)l1 << 16);
}

// -------- main warp-MMA implicit GEMM -------------------------------------
// EPI==0: A = im2col(x) produced in-kernel (m-major smem); out -> g_Y
// EPI==1: A = pre-sampled bf16 planes, pure copy (k-major smem); out -> NCHW
// CTA: 128 pixels x 256 channels, K = 2304. 512 threads / 16 warps (4m x 4n).
template <int EPI>
__global__ __launch_bounds__(512, 1) void mma_kernel(
    const float* __restrict__ x,
    const float* __restrict__ ba,
    const float* __restrict__ bb,
    float* __restrict__ Cout)
{
    extern __shared__ __align__(16) char smem[];
    const uint32_t sb = smem_u32(smem);
    const int tid  = threadIdx.x;
    const int lane = tid & 31;
    const int wid  = tid >> 5;
    const int wm   = wid & 3;      // warp m-index (x32)
    const int wn   = wid >> 2;     // warp n-index (x64)
    const int m0   = blockIdx.x * 128;
    const int b    = m0 >> 12;

    // EPI0 producer mapping: (m, word w) for m and m+64
    const int pm = tid >> 3;       // 0..63
    const int pw = tid & 7;        // word 0..7 (k = c*16 + pw*2)

    // EPI1 A-copy mapping: (plane, k-row, 16B seg)
    const int cs  = tid & 15;            // seg
    const int ckl = (tid >> 4) & 15;     // k-row
    const int cpl = tid >> 8;            // 0 hi, 1 lo

    // ---- ldmatrix per-lane offsets ----
    int offAh[2], offBh[4];
    if (EPI == 0) {
        const int rA   = lane & 15;
        const int segA = lane >> 4;
#pragma unroll
        for (int mt = 0; mt < 2; mt++) {
            int row = wm * 32 + mt * 16 + rA;
            offAh[mt] = AH_O + row * 32 + (((segA * 4) ^ (rA & 4)) << 2);
        }
    } else {
        const int kr = (lane & 7) + ((lane & 16) ? 8 : 0);
        const int mo = (lane & 8) ? 1 : 0;
#pragma unroll
        for (int mt = 0; mt < 2; mt++) {
            int mseg = wm * 4 + mt * 2 + mo;
            offAh[mt] = AH_O + kr * 256 + ((mseg ^ (kr & 7)) << 4);
        }
    }
    {
        const int rB   = (lane & 7) + ((lane & 16) ? 8 : 0);
        const int segB = (lane >> 3) & 1;
#pragma unroll
        for (int ntp = 0; ntp < 4; ntp++) {
            int row = wn * 64 + ntp * 16 + rB;
            offBh[ntp] = BH_O + row * 32 + (((segB * 4) ^ (rB & 4)) << 2);
        }
    }

    // B-copy mapping
    const int bn = tid >> 1;
    const int bq = tid & 1;

    float cr[2][8][4];
#pragma unroll
    for (int mt = 0; mt < 2; mt++)
#pragma unroll
        for (int nt = 0; nt < 8; nt++)
#pragma unroll
            for (int j = 0; j < 4; j++) cr[mt][nt][j] = 0.f;

    const uint32_t* __restrict__ Bh = g_Bw[EPI][0];
    const uint32_t* __restrict__ Bl = g_Bw[EPI][1];

    auto produce = [&](int c) {
        char* stp = smem + (c & 1) * STG_B;
        // ---- B tile copy (hi/lo) ----
        {
            int gw = bn * KW + c * 8 + bq * 4;
            uint4 vh = *(const uint4*)&Bh[gw];
            uint4 vl = *(const uint4*)&Bl[gw];
            int dw = bn * 8 + ((bq * 4) ^ (bn & 4));
            *(uint4*)(stp + BH_O + dw * 4) = vh;
            *(uint4*)(stp + BL_O + dw * 4) = vl;
        }
        if (EPI == 0) {
            // ---- A produce: im2col, 2 (m, word) pairs, m-major swizzled ----
#pragma unroll
            for (int half = 0; half < 2; half++) {
                const int m  = pm + half * 64;
                const int mg = m0 + m;
                const int k  = c * 16 + pw * 2;
                const int hh = (mg & 4095) >> 6;
                const int ww = mg & 63;
                float v0, v1;
#pragma unroll
                for (int u = 0; u < 2; u++) {
                    int kk  = k + u;
                    int ci  = kk / 9;
                    int tap = kk - ci * 9;
                    int dy = tap / 3 - 1, dx = tap - (tap / 3) * 3 - 1;
                    int y = hh + dy, xx2 = ww + dx;
                    float v = ((unsigned)y < (unsigned)HH &&
                               (unsigned)xx2 < (unsigned)WW)
                        ? x[((size_t)(b * CC + ci) << 12) + (y << 6) + xx2] : 0.f;
                    if (u == 0) v0 = v; else v1 = v;
                }
                uint16_t h0, l0, h1, l1;
                split_bf16(v0, h0, l0);
                split_bf16(v1, h1, l1);
                int dw = m * 8 + (pw ^ (m & 4));
                *(uint32_t*)(stp + AH_O + dw * 4) = (uint32_t)h0 | ((uint32_t)h1 << 16);
                *(uint32_t*)(stp + AL_O + dw * 4) = (uint32_t)l0 | ((uint32_t)l1 << 16);
            }
        } else {
            // ---- A copy: pre-sampled planes, k-major swizzled ----
            const uint16_t* src = (cpl ? g_Al : g_Ah)
                + (size_t)(c * 16 + ckl) * NPIX + m0 + cs * 8;
            uint4 v = *(const uint4*)src;
            *(uint4*)(stp + (cpl ? AL_O : AH_O) + ckl * 256
                      + ((cs ^ (ckl & 7)) << 4)) = v;
        }
    };

    produce(0);
    __syncthreads();

    for (int c = 0; c < NCH; c++) {
        if (c + 1 < NCH) produce(c + 1);          // fills buf (c+1)&1

        // ---- consume buf c&1 ----
        const uint32_t stb = sb + (c & 1) * STG_B;
        uint32_t ah[2][4], al[2][4];
#pragma unroll
        for (int mt = 0; mt < 2; mt++) {
            if (EPI == 0) {
                ldsm4(ah[mt], stb + offAh[mt]);
                ldsm4(al[mt], stb + offAh[mt] + (AL_O - AH_O));
            } else {
                ldsm4t(ah[mt], stb + offAh[mt]);
                ldsm4t(al[mt], stb + offAh[mt] + (AL_O - AH_O));
            }
        }
#pragma unroll
        for (int ntp = 0; ntp < 4; ntp++) {
            uint32_t bh[4], bl[4];
            ldsm4(bh, stb + offBh[ntp]);
            ldsm4(bl, stb + offBh[ntp] + (BL_O - BH_O));
#pragma unroll
            for (int j = 0; j < 2; j++) {
                const int nt = ntp * 2 + j;
#pragma unroll
                for (int mt = 0; mt < 2; mt++) {
                    float* cc = cr[mt][nt];
                    mma16816(cc, ah[mt], bh[2 * j], bh[2 * j + 1]);
                    mma16816(cc, ah[mt], bl[2 * j], bl[2 * j + 1]);
                    mma16816(cc, al[mt], bh[2 * j], bh[2 * j + 1]);
                }
            }
        }
        __syncthreads();
    }

    // ---- epilogue ----
    const int eg = lane >> 2;
    const int et = lane & 3;
#pragma unroll
    for (int mt = 0; mt < 2; mt++) {
#pragma unroll
        for (int nt = 0; nt < 8; nt++) {
            const float* cc = cr[mt][nt];
            int mloc = wm * 32 + mt * 16 + eg;
            int co   = wn * 64 + nt * 8 + et * 2;
#pragma unroll
            for (int rr = 0; rr < 2; rr++) {
                int m = m0 + mloc + rr * 8;
#pragma unroll
                for (int cw = 0; cw < 2; cw++) {
                    int c2 = co + cw;
                    float v = cc[rr * 2 + cw];
                    if (EPI == 0) {
                        if (c2 < CO1) {
                            float bias = (c2 < 144) ? ba[c2] : bb[c2 - 144];
                            g_Y[(size_t)c2 * NPIX + m] = v + bias;
                        }
                    } else {
                        Cout[((size_t)(b * OO + c2) << 12) + (m & 4095)] = v + ba[c2];
                    }
                }
            }
        }
    }
}

// -------- softmax + offsets -> packed bilinear weights/indices ------------
__global__ __launch_bounds__(256) void offmask_kernel() {
    int n = blockIdx.x * 256 + threadIdx.x;
    int g = blockIdx.y;
    int hw = n & 4095;
    int h = hw >> 6, w = hw & 63;

    float lg[KKT];
    float mx = -1e30f;
#pragma unroll
    for (int kk = 0; kk < KKT; kk++) {
        lg[kk] = g_Y[(size_t)(144 + g * KKT + kk) * NPIX + n];
        mx = fmaxf(mx, lg[kk]);
    }
    float s = 0.f;
#pragma unroll
    for (int kk = 0; kk < KKT; kk++) { lg[kk] = __expf(lg[kk] - mx); s += lg[kk]; }
    float inv = 1.f / s;

#pragma unroll
    for (int kk = 0; kk < KKT; kk++) {
        float a  = lg[kk] * inv;
        float dy = g_Y[(size_t)(g * 18 + 2 * kk    ) * NPIX + n];
        float dx = g_Y[(size_t)(g * 18 + 2 * kk + 1) * NPIX + n];
        float py = (float)(h - 1 + kk / 3) + dy;
        float px = (float)(w - 1 + kk % 3) + dx;

        float y0f = floorf(py), x0f = floorf(px);
        float fy = py - y0f, fx = px - x0f;
        y0f = fminf(fmaxf(y0f, -2.f), 65.f);
        x0f = fminf(fmaxf(x0f, -2.f), 65.f);
        int y0 = (int)y0f, x0 = (int)x0f;

        bool vy0 = (unsigned)y0       < (unsigned)HH;
        bool vy1 = (unsigned)(y0 + 1) < (unsigned)HH;
        bool vx0 = (unsigned)x0       < (unsigned)WW;
        bool vx1 = (unsigned)(x0 + 1) < (unsigned)WW;

        float w00 = (vy0 && vx0) ? (1.f - fy) * (1.f - fx) * a : 0.f;
        float w01 = (vy0 && vx1) ? (1.f - fy) * fx * a : 0.f;
        float w10 = (vy1 && vx0) ? fy * (1.f - fx) * a : 0.f;
        float w11 = (vy1 && vx1) ? fy * fx * a : 0.f;

        int r0  = min(max(y0,     0), HH - 1);
        int r1  = min(max(y0 + 1, 0), HH - 1);
        int cc0 = min(max(x0,     0), WW - 1);
        int cc1 = min(max(x0 + 1, 0), WW - 1);
        int pack = r0 | (r1 << 6) | (cc0 << 12) | (cc1 << 18);

        size_t o = (size_t)(g * KKT + kk) * NPIX + n;
        g_wq[o]  = make_float4(w00, w01, w10, w11);
        g_idx[o] = pack;
    }
}

// -------- sampler: wq/idx once per (pixel,g,tap), loop cg, write planes ---
__global__ __launch_bounds__(256) void sample_kernel(const float* __restrict__ x) {
    int n  = blockIdx.x * 256 + threadIdx.x;
    int gk = blockIdx.y;               // 0..71
    int g = gk / KKT, tap = gk - g * KKT;
    int b = n >> 12;

    size_t sidx = (size_t)gk * NPIX + n;
    float4 wq = g_wq[sidx];
    int pk = g_idx[sidx];
    int r0 = pk & 63, r1 = (pk >> 6) & 63;
    int c0 = (pk >> 12) & 63, c1 = (pk >> 18) & 63;
    int o00 = (r0 << 6) + c0, o01 = (r0 << 6) + c1;
    int o10 = (r1 << 6) + c0, o11 = (r1 << 6) + c1;

    const float* xb = x + ((size_t)(b * CC + g * CGR) << 12);
    const int kbase = g * 288 + tap;
#pragma unroll 4
    for (int cg = 0; cg < CGR; cg++) {
        const float* p = xb + ((size_t)cg << 12);
        float v = wq.x * p[o00] + wq.y * p[o01] + wq.z * p[o10] + wq.w * p[o11];
        uint16_t h, l;
        split_bf16(v, h, l);
        size_t a = (size_t)(kbase + cg * 9) * NPIX + n;
        g_Ah[a] = h;
        g_Al[a] = l;
    }
}

// --------------------------------------------------------------------------
extern "C" void kernel_launch(void* const* d_in, const int* in_sizes, int n_in,
                              void* d_out, int out_size) {
    const float* x      = nullptr;
    const float* w_off  = nullptr;
    const float* b_off  = nullptr;
    const float* w_attn = nullptr;
    const float* b_attn = nullptr;
    const float* w_out  = nullptr;
    const float* b_out  = nullptr;
    for (int i = 0; i < n_in; i++) {
        const float* p = (const float*)d_in[i];
        switch (in_sizes[i]) {
            case 8388608: x      = p; break;
            case 331776:  w_off  = p; break;
            case 144:     b_off  = p; break;
            case 165888:  w_attn = p; break;
            case 72:      b_attn = p; break;
            case 589824:  w_out  = p; break;
            case 256:     b_out  = p; break;
            default: break;
        }
    }
    if (!x || !w_off || !b_off || !w_attn || !b_attn || !w_out || !b_out)
        return;
    float* out = (float*)d_out;

    cudaFuncSetAttribute(mma_kernel<0>,
        cudaFuncAttributeMaxDynamicSharedMemorySize, SMEM_TOT);
    cudaFuncSetAttribute(mma_kernel<1>,
        cudaFuncAttributeMaxDynamicSharedMemorySize, SMEM_TOT);

    // 0) stage weights: fp32 -> bf16 hi/lo packed word pairs
    stageB_kernel<<<(2 * 256 * KW) / 256, 256>>>(w_off, w_attn, w_out);

    // 1) offset/mask conv (HMMA, fused im2col) -> g_Y
    mma_kernel<0><<<NPIX / 128, 512, SMEM_TOT>>>(x, b_off, b_attn, nullptr);

    // 2) softmax + packed bilinear weights/indices
    offmask_kernel<<<dim3(NPIX / 256, GG), 256>>>();

    // 3) sampling pass: modulated bilinear gather -> bf16 hi/lo planes
    sample_kernel<<<dim3(NPIX / 256, GG * KKT), 256>>>(x);

    // 4) deformable conv (HMMA, A = plane copy) -> NCHW out
    mma_kernel<1><<<NPIX / 128, 512, SMEM_TOT>>>(x, b_out, nullptr, out);
}

// round 8
// speedup vs baseline: 2.4176x; 1.1386x over previous
#include <cuda_runtime.h>
#include <cuda_bf16.h>
#include <cstdint>
#include <cstddef>

#define BB 8
#define CC 256
#define HH 64
#define WW 64
#define GG 8
#define CGR 32
#define KKT 9
#define OO 256
#define NPIX (BB*HH*WW)        // 32768
#define KC (CC*KKT)            // 2304
#define KW (KC/2)              // 1152 b32 words per row
#define CO1 216
#define HWSZ (HH*WW)           // 4096
#define NCH (KC/16)            // 144 k16 steps

// smem rings: B 4 stages x 16KB (hi 8K | lo 8K); A at +64KB: stages x 8KB (hi 4K | lo 4K)
#define B_STG_B 16384
#define A_BASE  65536
#define A_STG_B 8192
#define SMEM_TOT (A_BASE + 4*A_STG_B)   // 98304

// -------- scratch (static device globals, ~382MB) -------------------------
__device__ __align__(16) float    g_Y[(size_t)CO1 * NPIX];          // conv1 out
__device__ __align__(16) float4   g_wq[(size_t)(GG*KKT) * NPIX];    // bilinear wts * attn
__device__ __align__(16) int      g_idx[(size_t)(GG*KKT) * NPIX];   // packed indices
__device__ __align__(16) uint32_t g_Bw[2][2][256 * KW];             // [gemm][hi/lo][n][kw]
__device__ __align__(16) uint16_t g_Ah[(size_t)KC * NPIX];          // sampled A hi plane
__device__ __align__(16) uint16_t g_Al[(size_t)KC * NPIX];          // sampled A lo plane

// -------- helpers ---------------------------------------------------------
__device__ __forceinline__ uint32_t smem_u32(const void* p) {
    uint32_t a;
    asm("{ .reg .u64 t; cvta.to.shared.u64 t, %1; cvt.u32.u64 %0, t; }"
        : "=r"(a) : "l"(p));
    return a;
}
__device__ __forceinline__ void cpasync16(uint32_t dst, const void* src) {
    asm volatile("cp.async.cg.shared.global [%0], [%1], 16;"
        :: "r"(dst), "l"(src) : "memory");
}
#define CP_COMMIT() asm volatile("cp.async.commit_group;" ::: "memory")
#define CP_WAIT2()  asm volatile("cp.async.wait_group 2;" ::: "memory")
#define CP_WAIT0()  asm volatile("cp.async.wait_group 0;" ::: "memory")
__device__ __forceinline__ void ldsm4(uint32_t* r, uint32_t addr) {
    asm volatile("ldmatrix.sync.aligned.m8n8.x4.shared.b16 {%0,%1,%2,%3}, [%4];"
        : "=r"(r[0]), "=r"(r[1]), "=r"(r[2]), "=r"(r[3]) : "r"(addr));
}
__device__ __forceinline__ void ldsm4t(uint32_t* r, uint32_t addr) {
    asm volatile("ldmatrix.sync.aligned.m8n8.x4.trans.shared.b16 {%0,%1,%2,%3}, [%4];"
        : "=r"(r[0]), "=r"(r[1]), "=r"(r[2]), "=r"(r[3]) : "r"(addr));
}
__device__ __forceinline__ void mma16816(float* c, const uint32_t* a,
                                         uint32_t b0, uint32_t b1) {
    asm volatile(
        "mma.sync.aligned.m16n8k16.row.col.f32.bf16.bf16.f32 "
        "{%0,%1,%2,%3}, {%4,%5,%6,%7}, {%8,%9}, {%0,%1,%2,%3};"
        : "+f"(c[0]), "+f"(c[1]), "+f"(c[2]), "+f"(c[3])
        : "r"(a[0]), "r"(a[1]), "r"(a[2]), "r"(a[3]), "r"(b0), "r"(b1));
}
__device__ __forceinline__ void split_bf16(float v, uint16_t& h, uint16_t& l) {
    __nv_bfloat16 hb = __float2bfloat16(v);
    float r = v - __bfloat162float(hb);
    __nv_bfloat16 lb = __float2bfloat16(r);
    h = *reinterpret_cast<uint16_t*>(&hb);
    l = *reinterpret_cast<uint16_t*>(&lb);
}

// -------- setup: split weights to bf16 hi/lo word pairs -------------------
__global__ __launch_bounds__(256) void stageB_kernel(
    const float* __restrict__ w_off, const float* __restrict__ w_attn,
    const float* __restrict__ w_out)
{
    int idx = blockIdx.x * 256 + threadIdx.x;     // over 2*256*1152
    int gemm = idx / (256 * KW);
    int rem  = idx - gemm * (256 * KW);
    int row  = rem / KW;
    int wd   = rem - row * KW;
    int k    = wd * 2;
    float v0 = 0.f, v1 = 0.f;
    if (gemm == 0) {
        if (row < 144) {
            v0 = w_off[(size_t)row * KC + k];
            v1 = w_off[(size_t)row * KC + k + 1];
        } else if (row < CO1) {
            v0 = w_attn[(size_t)(row - 144) * KC + k];
            v1 = w_attn[(size_t)(row - 144) * KC + k + 1];
        }
    } else {
        v0 = w_out[(size_t)row * KC + k];
        v1 = w_out[(size_t)row * KC + k + 1];
    }
    uint16_t h0, l0, h1, l1;
    split_bf16(v0, h0, l0);
    split_bf16(v1, h1, l1);
    g_Bw[gemm][0][row * KW + wd] = (uint32_t)h0 | ((uint32_t)h1 << 16);
    g_Bw[gemm][1][row * KW + wd] = (uint32_t)l0 | ((uint32_t)l1 << 16);
}

// -------- main warp-MMA implicit GEMM -------------------------------------
// EPI==0: A = im2col(x) computed in-kernel (2-stage STS ring); B cp.async 4-stage
// EPI==1: A & B pure cp.async copies, both 4-stage rings
// CTA: 128 pixels x 256 channels, K = 2304. 512 threads / 16 warps (4m x 4n).
template <int EPI>
__global__ __launch_bounds__(512, 1) void mma_kernel(
    const float* __restrict__ x,
    const float* __restrict__ ba,
    const float* __restrict__ bb,
    float* __restrict__ Cout)
{
    constexpr int ASTG = (EPI == 0) ? 2 : 4;
    extern __shared__ __align__(16) char smem[];
    const uint32_t sb = smem_u32(smem);
    const int tid  = threadIdx.x;
    const int lane = tid & 31;
    const int wid  = tid >> 5;
    const int wm   = wid & 3;      // warp m-index (x32)
    const int wn   = wid >> 2;     // warp n-index (x64)
    const int m0   = blockIdx.x * 128;
    const int b    = m0 >> 12;

    // EPI0 producer mapping: (m, word w) for m and m+64
    const int pm = tid >> 3;       // 0..63
    const int pw = tid & 7;        // word 0..7 (k = c*16 + pw*2)

    // EPI1 A-copy mapping: (plane, k-row, 16B seg)
    const int cs  = tid & 15;            // seg
    const int ckl = (tid >> 4) & 15;     // k-row
    const int cpl = tid >> 8;            // 0 hi, 1 lo

    // ---- ldmatrix per-lane offsets (relative to stage bases) ----
    int offAh[2], offBh[4];
    if (EPI == 0) {
        const int rA   = lane & 15;
        const int segA = lane >> 4;
#pragma unroll
        for (int mt = 0; mt < 2; mt++) {
            int row = wm * 32 + mt * 16 + rA;
            offAh[mt] = row * 32 + (((segA * 4) ^ (rA & 4)) << 2);
        }
    } else {
        const int kr = (lane & 7) + ((lane & 16) ? 8 : 0);
        const int mo = (lane & 8) ? 1 : 0;
#pragma unroll
        for (int mt = 0; mt < 2; mt++) {
            int mseg = wm * 4 + mt * 2 + mo;
            offAh[mt] = kr * 256 + ((mseg ^ (kr & 7)) << 4);
        }
    }
    {
        const int rB   = (lane & 7) + ((lane & 16) ? 8 : 0);
        const int segB = (lane >> 3) & 1;
#pragma unroll
        for (int ntp = 0; ntp < 4; ntp++) {
            int row = wn * 64 + ntp * 16 + rB;
            offBh[ntp] = row * 32 + (((segB * 4) ^ (rB & 4)) << 2);
        }
    }

    // B-copy mapping
    const int bn = tid >> 1;
    const int bq = tid & 1;
    const int bdw = (bn * 8 + ((bq * 4) ^ (bn & 4))) * 4;  // byte offset in plane

    float cr[2][8][4];
#pragma unroll
    for (int mt = 0; mt < 2; mt++)
#pragma unroll
        for (int nt = 0; nt < 8; nt++)
#pragma unroll
            for (int j = 0; j < 4; j++) cr[mt][nt][j] = 0.f;

    const uint32_t* __restrict__ Bh = g_Bw[EPI][0];
    const uint32_t* __restrict__ Bl = g_Bw[EPI][1];

    // ---- async producers ----
    auto cpB = [&](int c) {
        if (c < NCH) {
            uint32_t dst = sb + (c & 3) * B_STG_B + bdw;
            const uint32_t* sh = &Bh[bn * KW + c * 8 + bq * 4];
            const uint32_t* sl = &Bl[bn * KW + c * 8 + bq * 4];
            cpasync16(dst, sh);
            cpasync16(dst + 8192, sl);
            if (EPI == 1) {
                uint32_t adst = sb + A_BASE + (c & 3) * A_STG_B + cpl * 4096
                              + ckl * 256 + ((cs ^ (ckl & 7)) << 4);
                const uint16_t* src = (cpl ? g_Al : g_Ah)
                    + (size_t)(c * 16 + ckl) * NPIX + m0 + cs * 8;
                cpasync16(adst, src);
            }
        }
        CP_COMMIT();
    };
    auto prodA0 = [&](int c) {      // EPI0 only: compute + STS
        if (c >= NCH) return;
        char* stp = smem + A_BASE + (c % ASTG) * A_STG_B;
#pragma unroll
        for (int half = 0; half < 2; half++) {
            const int m  = pm + half * 64;
            const int mg = m0 + m;
            const int k  = c * 16 + pw * 2;
            const int hh = (mg & 4095) >> 6;
            const int ww = mg & 63;
            float v0, v1;
#pragma unroll
            for (int u = 0; u < 2; u++) {
                int kk  = k + u;
                int ci  = kk / 9;
                int tap = kk - ci * 9;
                int dy = tap / 3 - 1, dx = tap - (tap / 3) * 3 - 1;
                int y = hh + dy, xx2 = ww + dx;
                float v = ((unsigned)y < (unsigned)HH &&
                           (unsigned)xx2 < (unsigned)WW)
                    ? x[((size_t)(b * CC + ci) << 12) + (y << 6) + xx2] : 0.f;
                if (u == 0) v0 = v; else v1 = v;
            }
            uint16_t h0, l0, h1, l1;
            split_bf16(v0, h0, l0);
            split_bf16(v1, h1, l1);
            int dw = m * 8 + (pw ^ (m & 4));
            *(uint32_t*)(stp +        dw * 4) = (uint32_t)h0 | ((uint32_t)h1 << 16);
            *(uint32_t*)(stp + 4096 + dw * 4) = (uint32_t)l0 | ((uint32_t)l1 << 16);
        }
    };

    // ---- prologue: 3 async groups in flight; EPI0 also computes A(0) ----
    cpB(0); cpB(1); cpB(2);
    if (EPI == 0) prodA0(0);

    for (int c = 0; c < NCH; c++) {
        CP_WAIT2();               // stage c resident
        __syncthreads();          // + all warps done reading recycled stages

        if (EPI == 0) prodA0(c + 1);
        cpB(c + 3);

        // ---- consume stage c ----
        const uint32_t stbB = sb + (c & 3) * B_STG_B;
        const uint32_t stbA = sb + A_BASE + (c % ASTG) * A_STG_B;
        uint32_t ah[2][4], al[2][4];
#pragma unroll
        for (int mt = 0; mt < 2; mt++) {
            if (EPI == 0) {
                ldsm4(ah[mt], stbA + offAh[mt]);
                ldsm4(al[mt], stbA + offAh[mt] + 4096);
            } else {
                ldsm4t(ah[mt], stbA + offAh[mt]);
                ldsm4t(al[mt], stbA + offAh[mt] + 4096);
            }
        }
#pragma unroll
        for (int ntp = 0; ntp < 4; ntp++) {
            uint32_t bh[4], bl[4];
            ldsm4(bh, stbB + offBh[ntp]);
            ldsm4(bl, stbB + offBh[ntp] + 8192);
#pragma unroll
            for (int j = 0; j < 2; j++) {
                const int nt = ntp * 2 + j;
#pragma unroll
                for (int mt = 0; mt < 2; mt++) {
                    float* cc = cr[mt][nt];
                    mma16816(cc, ah[mt], bh[2 * j], bh[2 * j + 1]);
                    mma16816(cc, ah[mt], bl[2 * j], bl[2 * j + 1]);
                    mma16816(cc, al[mt], bh[2 * j], bh[2 * j + 1]);
                }
            }
        }
    }
    CP_WAIT0();

    // ---- epilogue ----
    const int eg = lane >> 2;
    const int et = lane & 3;
#pragma unroll
    for (int mt = 0; mt < 2; mt++) {
#pragma unroll
        for (int nt = 0; nt < 8; nt++) {
            const float* cc = cr[mt][nt];
            int mloc = wm * 32 + mt * 16 + eg;
            int co   = wn * 64 + nt * 8 + et * 2;
#pragma unroll
            for (int rr = 0; rr < 2; rr++) {
                int m = m0 + mloc + rr * 8;
#pragma unroll
                for (int cw = 0; cw < 2; cw++) {
                    int c2 = co + cw;
                    float v = cc[rr * 2 + cw];
                    if (EPI == 0) {
                        if (c2 < CO1) {
                            float bias = (c2 < 144) ? ba[c2] : bb[c2 - 144];
                            g_Y[(size_t)c2 * NPIX + m] = v + bias;
                        }
                    } else {
                        Cout[((size_t)(b * OO + c2) << 12) + (m & 4095)] = v + ba[c2];
                    }
                }
            }
        }
    }
}

// -------- softmax + offsets -> packed bilinear weights/indices ------------
__global__ __launch_bounds__(256) void offmask_kernel() {
    int n = blockIdx.x * 256 + threadIdx.x;
    int g = blockIdx.y;
    int hw = n & 4095;
    int h = hw >> 6, w = hw & 63;

    float lg[KKT];
    float mx = -1e30f;
#pragma unroll
    for (int kk = 0; kk < KKT; kk++) {
        lg[kk] = g_Y[(size_t)(144 + g * KKT + kk) * NPIX + n];
        mx = fmaxf(mx, lg[kk]);
    }
    float s = 0.f;
#pragma unroll
    for (int kk = 0; kk < KKT; kk++) { lg[kk] = __expf(lg[kk] - mx); s += lg[kk]; }
    float inv = 1.f / s;

#pragma unroll
    for (int kk = 0; kk < KKT; kk++) {
        float a  = lg[kk] * inv;
        float dy = g_Y[(size_t)(g * 18 + 2 * kk    ) * NPIX + n];
        float dx = g_Y[(size_t)(g * 18 + 2 * kk + 1) * NPIX + n];
        float py = (float)(h - 1 + kk / 3) + dy;
        float px = (float)(w - 1 + kk % 3) + dx;

        float y0f = floorf(py), x0f = floorf(px);
        float fy = py - y0f, fx = px - x0f;
        y0f = fminf(fmaxf(y0f, -2.f), 65.f);
        x0f = fminf(fmaxf(x0f, -2.f), 65.f);
        int y0 = (int)y0f, x0 = (int)x0f;

        bool vy0 = (unsigned)y0       < (unsigned)HH;
        bool vy1 = (unsigned)(y0 + 1) < (unsigned)HH;
        bool vx0 = (unsigned)x0       < (unsigned)WW;
        bool vx1 = (unsigned)(x0 + 1) < (unsigned)WW;

        float w00 = (vy0 && vx0) ? (1.f - fy) * (1.f - fx) * a : 0.f;
        float w01 = (vy0 && vx1) ? (1.f - fy) * fx * a : 0.f;
        float w10 = (vy1 && vx0) ? fy * (1.f - fx) * a : 0.f;
        float w11 = (vy1 && vx1) ? fy * fx * a : 0.f;

        int r0  = min(max(y0,     0), HH - 1);
        int r1  = min(max(y0 + 1, 0), HH - 1);
        int cc0 = min(max(x0,     0), WW - 1);
        int cc1 = min(max(x0 + 1, 0), WW - 1);
        int pack = r0 | (r1 << 6) | (cc0 << 12) | (cc1 << 18);

        size_t o = (size_t)(g * KKT + kk) * NPIX + n;
        g_wq[o]  = make_float4(w00, w01, w10, w11);
        g_idx[o] = pack;
    }
}

// -------- sampler: wq/idx once per (pixel,g,tap), loop cg, write planes ---
__global__ __launch_bounds__(256) void sample_kernel(const float* __restrict__ x) {
    int n  = blockIdx.x * 256 + threadIdx.x;
    int gk = blockIdx.y;               // 0..71
    int g = gk / KKT, tap = gk - g * KKT;
    int b = n >> 12;

    size_t sidx = (size_t)gk * NPIX + n;
    float4 wq = g_wq[sidx];
    int pk = g_idx[sidx];
    int r0 = pk & 63, r1 = (pk >> 6) & 63;
    int c0 = (pk >> 12) & 63, c1 = (pk >> 18) & 63;
    int o00 = (r0 << 6) + c0, o01 = (r0 << 6) + c1;
    int o10 = (r1 << 6) + c0, o11 = (r1 << 6) + c1;

    const float* xb = x + ((size_t)(b * CC + g * CGR) << 12);
    const int kbase = g * 288 + tap;
#pragma unroll 4
    for (int cg = 0; cg < CGR; cg++) {
        const float* p = xb + ((size_t)cg << 12);
        float v = wq.x * p[o00] + wq.y * p[o01] + wq.z * p[o10] + wq.w * p[o11];
        uint16_t h, l;
        split_bf16(v, h, l);
        size_t a = (size_t)(kbase + cg * 9) * NPIX + n;
        g_Ah[a] = h;
        g_Al[a] = l;
    }
}

// --------------------------------------------------------------------------
extern "C" void kernel_launch(void* const* d_in, const int* in_sizes, int n_in,
                              void* d_out, int out_size) {
    const float* x      = nullptr;
    const float* w_off  = nullptr;
    const float* b_off  = nullptr;
    const float* w_attn = nullptr;
    const float* b_attn = nullptr;
    const float* w_out  = nullptr;
    const float* b_out  = nullptr;
    for (int i = 0; i < n_in; i++) {
        const float* p = (const float*)d_in[i];
        switch (in_sizes[i]) {
            case 8388608: x      = p; break;
            case 331776:  w_off  = p; break;
            case 144:     b_off  = p; break;
            case 165888:  w_attn = p; break;
            case 72:      b_attn = p; break;
            case 589824:  w_out  = p; break;
            case 256:     b_out  = p; break;
            default: break;
        }
    }
    if (!x || !w_off || !b_off || !w_attn || !b_attn || !w_out || !b_out)
        return;
    float* out = (float*)d_out;

    cudaFuncSetAttribute(mma_kernel<0>,
        cudaFuncAttributeMaxDynamicSharedMemorySize, SMEM_TOT);
    cudaFuncSetAttribute(mma_kernel<1>,
        cudaFuncAttributeMaxDynamicSharedMemorySize, SMEM_TOT);

    // 0) stage weights: fp32 -> bf16 hi/lo packed word pairs
    stageB_kernel<<<(2 * 256 * KW) / 256, 256>>>(w_off, w_attn, w_out);

    // 1) offset/mask conv (HMMA, fused im2col, cp.async B) -> g_Y
    mma_kernel<0><<<NPIX / 128, 512, SMEM_TOT>>>(x, b_off, b_attn, nullptr);

    // 2) softmax + packed bilinear weights/indices
    offmask_kernel<<<dim3(NPIX / 256, GG), 256>>>();

    // 3) sampling pass: modulated bilinear gather -> bf16 hi/lo planes
    sample_kernel<<<dim3(NPIX / 256, GG * KKT), 256>>>(x);

    // 4) deformable conv (HMMA, A/B cp.async 4-stage) -> NCHW out
    mma_kernel<1><<<NPIX / 128, 512, SMEM_TOT>>>(x, b_out, nullptr, out);
}